// round 15
// baseline (speedup 1.0000x reference)
#include <cuda_runtime.h>

// ---------------- problem constants ----------------
#define N_NODES 10000
#define N_EDGES 320000
#define D       256
#define D4      1024   // 4*D (LSTM gates)
#define HDIM    128    // MLP hidden
#define NUM_REL 2

// ---------------- scratch (device globals; no allocation allowed) ----------
__device__ float g_H1[NUM_REL * N_NODES * D];    // 20 MB
__device__ float g_M2[NUM_REL * N_NODES * D];    // 20 MB
__device__ float g_agg[N_NODES * D];             // 10 MB
__device__ float g_gates[N_NODES * D4];          // 40 MB
__device__ float g_hn[N_NODES * D];              // 10 MB
__device__ float g_x1[N_NODES * HDIM];           // 5 MB
__device__ float g_x2[N_NODES * HDIM];           // 5 MB
__device__ int   g_counts[N_NODES];
__device__ int   g_off[N_NODES];
__device__ int   g_cursor[N_NODES];
__device__ int   g_edges[N_EDGES];

// ---------------- f32x2 packed-FMA helpers (Blackwell sm_103a) -------------
__device__ __forceinline__ unsigned long long pack2(float x) {
    unsigned long long r;
    unsigned int xi = __float_as_uint(x);
    asm("mov.b64 %0, {%1, %1};" : "=l"(r) : "r"(xi));
    return r;
}
__device__ __forceinline__ void ffma2(unsigned long long& d,
                                      unsigned long long a,
                                      unsigned long long b) {
    asm("fma.rn.f32x2 %0, %1, %2, %0;" : "+l"(d) : "l"(a), "l"(b));
}
__device__ __forceinline__ float2 unpack2(unsigned long long v) {
    unsigned int lo, hi;
    asm("mov.b64 {%0, %1}, %2;" : "=r"(lo), "=r"(hi) : "l"(v));
    return make_float2(__uint_as_float(lo), __uint_as_float(hi));
}

// ---------------- GEMM: C[M,N] = act(A[M,K] @ B[N,K]^T + bias (+bias2)) ----
// Block tile 64x128, BK=16, 256 threads, 4x8 micro-tile using packed f32x2.
#define BM 64
#define BN 128
#define BK 16

__global__ __launch_bounds__(256, 2)
void gemm_kernel(const float* __restrict__ A, long long aStrideZ,
                 const float* __restrict__ B, long long bStrideZ,
                 const float* __restrict__ bias, long long biasStrideZ,
                 const float* __restrict__ bias2,
                 float* __restrict__ C, long long cStrideZ,
                 int M, int N, int K, int act)
{
    __shared__ __align__(16) float As[BK][BM];
    __shared__ __align__(16) float Bs[BK][BN];

    const int z = blockIdx.z;
    A    += (long long)z * aStrideZ;
    B    += (long long)z * bStrideZ;
    bias += (long long)z * biasStrideZ;
    C    += (long long)z * cStrideZ;

    const int t  = threadIdx.x;        // 0..255
    const int tx = t & 15;             // 0..15  -> 8 output cols
    const int ty = t >> 4;             // 0..15  -> 4 output rows
    const int m0 = blockIdx.x * BM;
    const int n0 = blockIdx.y * BN;

    // A-tile load mapping: 64x16 floats, 4 per thread (float4 along K)
    const int am = t >> 2;             // 0..63
    const int ak = (t & 3) * 4;        // 0,4,8,12

    unsigned long long acc[4][4];
#pragma unroll
    for (int i = 0; i < 4; i++)
#pragma unroll
        for (int j = 0; j < 4; j++) acc[i][j] = 0ULL;

    for (int kk = 0; kk < K; kk += BK) {
        // ---- stage A tile (guard M) ----
        float4 av;
        if (m0 + am < M)
            av = *(const float4*)&A[(long long)(m0 + am) * K + kk + ak];
        else
            av = make_float4(0.f, 0.f, 0.f, 0.f);
        As[ak + 0][am] = av.x;
        As[ak + 1][am] = av.y;
        As[ak + 2][am] = av.z;
        As[ak + 3][am] = av.w;

        // ---- stage B tile: 128x16 floats, 8 per thread ----
#pragma unroll
        for (int it = 0; it < 2; it++) {
            int idx = t + it * 256;
            int bn  = idx >> 2;        // 0..127
            int bk  = (idx & 3) * 4;
            float4 bv = *(const float4*)&B[(long long)(n0 + bn) * K + kk + bk];
            Bs[bk + 0][bn] = bv.x;
            Bs[bk + 1][bn] = bv.y;
            Bs[bk + 2][bn] = bv.z;
            Bs[bk + 3][bn] = bv.w;
        }
        __syncthreads();

        // ---- 4x8 micro-kernel over BK, packed f32x2 FMAs ----
#pragma unroll
        for (int k = 0; k < BK; k++) {
            float4 a4 = *(const float4*)&As[k][ty * 4];
            unsigned long long a0 = pack2(a4.x);
            unsigned long long a1 = pack2(a4.y);
            unsigned long long a2 = pack2(a4.z);
            unsigned long long a3 = pack2(a4.w);
            const ulonglong2* bp =
                reinterpret_cast<const ulonglong2*>(&Bs[k][tx * 8]);
            ulonglong2 b01 = bp[0];
            ulonglong2 b23 = bp[1];
            ffma2(acc[0][0], a0, b01.x); ffma2(acc[0][1], a0, b01.y);
            ffma2(acc[0][2], a0, b23.x); ffma2(acc[0][3], a0, b23.y);
            ffma2(acc[1][0], a1, b01.x); ffma2(acc[1][1], a1, b01.y);
            ffma2(acc[1][2], a1, b23.x); ffma2(acc[1][3], a1, b23.y);
            ffma2(acc[2][0], a2, b01.x); ffma2(acc[2][1], a2, b01.y);
            ffma2(acc[2][2], a2, b23.x); ffma2(acc[2][3], a2, b23.y);
            ffma2(acc[3][0], a3, b01.x); ffma2(acc[3][1], a3, b01.y);
            ffma2(acc[3][2], a3, b23.x); ffma2(acc[3][3], a3, b23.y);
        }
        __syncthreads();
    }

    // ---- epilogue: bias (+bias2), optional relu, vectorized store ----
    float bv[8];
#pragma unroll
    for (int j = 0; j < 8; j++) {
        int c = n0 + tx * 8 + j;
        float b = bias[c];
        if (bias2) b += bias2[c];
        bv[j] = b;
    }
#pragma unroll
    for (int i = 0; i < 4; i++) {
        int row = m0 + ty * 4 + i;
        if (row >= M) break;
        float o[8];
#pragma unroll
        for (int j = 0; j < 4; j++) {
            float2 p = unpack2(acc[i][j]);
            o[2 * j + 0] = p.x + bv[2 * j + 0];
            o[2 * j + 1] = p.y + bv[2 * j + 1];
        }
        if (act) {
#pragma unroll
            for (int j = 0; j < 8; j++) o[j] = fmaxf(o[j], 0.f);
        }
        float4* cp = (float4*)&C[(long long)row * N + n0 + tx * 8];
        cp[0] = make_float4(o[0], o[1], o[2], o[3]);
        cp[1] = make_float4(o[4], o[5], o[6], o[7]);
    }
}

// ---------------- CSR construction ----------------
__global__ void zero_counts_kernel() {
    int i = blockIdx.x * blockDim.x + threadIdx.x;
    if (i < N_NODES) g_counts[i] = 0;
}

__global__ void hist_kernel(const int* __restrict__ dst) {
    int e = blockIdx.x * blockDim.x + threadIdx.x;
    if (e < N_EDGES) atomicAdd(&g_counts[dst[e]], 1);
}

__global__ void scan_kernel() {
    __shared__ int sums[1024];
    const int t = threadIdx.x;
    const int CH = (N_NODES + 1023) / 1024;   // 10
    const int base = t * CH;
    int s = 0;
#pragma unroll
    for (int i = 0; i < CH; i++)
        if (base + i < N_NODES) s += g_counts[base + i];
    sums[t] = s;
    __syncthreads();
    for (int off = 1; off < 1024; off <<= 1) {
        int v = (t >= off) ? sums[t - off] : 0;
        __syncthreads();
        sums[t] += v;
        __syncthreads();
    }
    int ex = (t == 0) ? 0 : sums[t - 1];
#pragma unroll
    for (int i = 0; i < CH; i++) {
        int n = base + i;
        if (n < N_NODES) {
            g_off[n]    = ex;
            g_cursor[n] = ex;
            ex += g_counts[n];
        }
    }
}

__global__ void scatter_kernel(const int* __restrict__ src,
                               const int* __restrict__ dst,
                               const int* __restrict__ rel) {
    int e = blockIdx.x * blockDim.x + threadIdx.x;
    if (e < N_EDGES) {
        int d   = dst[e];
        int pos = atomicAdd(&g_cursor[d], 1);
        g_edges[pos] = (rel[e] << 16) | src[e];
    }
}

// ---------------- aggregation: one warp per destination node ---------------
__global__ void aggregate_kernel() {
    int node = (blockIdx.x * blockDim.x + threadIdx.x) >> 5;
    int lane = threadIdx.x & 31;
    if (node >= N_NODES) return;
    int start = g_off[node];
    int cnt   = g_counts[node];
    float4 a0 = make_float4(0.f, 0.f, 0.f, 0.f);
    float4 a1 = a0;
    for (int e = 0; e < cnt; e++) {
        int p = g_edges[start + e];
        const float4* row = (const float4*)
            &g_M2[((long long)(p >> 16) * N_NODES + (p & 0xFFFF)) * D];
        float4 v0 = row[lane];
        float4 v1 = row[lane + 32];
        a0.x += v0.x; a0.y += v0.y; a0.z += v0.z; a0.w += v0.w;
        a1.x += v1.x; a1.y += v1.y; a1.z += v1.z; a1.w += v1.w;
    }
    float4* outp = (float4*)&g_agg[(long long)node * D];
    outp[lane]      = a0;
    outp[lane + 32] = a1;
}

// ---------------- per-node LSTM step from zero state ----------------
__device__ __forceinline__ float sigmoidf_(float x) {
    return 1.f / (1.f + expf(-x));
}

__global__ void lstm_kernel() {
    int idx = blockIdx.x * blockDim.x + threadIdx.x;
    if (idx >= N_NODES * D) return;
    int n = idx >> 8;        // /256
    int d = idx & 255;
    const float* g = &g_gates[(long long)n * D4];
    float gi = g[d];
    float gg = g[2 * D + d];
    float go = g[3 * D + d];
    float c  = sigmoidf_(gi) * tanhf(gg);
    g_hn[idx] = sigmoidf_(go) * tanhf(c);
}

// ---------------- launch ----------------
extern "C" void kernel_launch(void* const* d_in, const int* in_sizes, int n_in,
                              void* d_out, int out_size)
{
    const float* feat  = (const float*)d_in[0];
    const int*   src   = (const int*)  d_in[1];
    const int*   dst   = (const int*)  d_in[2];
    const int*   rel   = (const int*)  d_in[3];
    const float* W_rel = (const float*)d_in[4];
    const float* b_rel = (const float*)d_in[5];
    const float* W_ih  = (const float*)d_in[6];
    const float* b_ih  = (const float*)d_in[7];
    const float* b_hh  = (const float*)d_in[8];
    const float* W1    = (const float*)d_in[9];
    const float* b1    = (const float*)d_in[10];
    const float* W2    = (const float*)d_in[11];
    const float* b2    = (const float*)d_in[12];
    const float* W3    = (const float*)d_in[13];
    const float* b3    = (const float*)d_in[14];
    float*       out   = (float*)d_out;

    float *H1, *M2, *agg, *gates, *hn, *x1, *x2;
    cudaGetSymbolAddress((void**)&H1,    g_H1);
    cudaGetSymbolAddress((void**)&M2,    g_M2);
    cudaGetSymbolAddress((void**)&agg,   g_agg);
    cudaGetSymbolAddress((void**)&gates, g_gates);
    cudaGetSymbolAddress((void**)&hn,    g_hn);
    cudaGetSymbolAddress((void**)&x1,    g_x1);
    cudaGetSymbolAddress((void**)&x2,    g_x2);

    const int GM = (N_NODES + BM - 1) / BM;   // 157
    dim3 blk(256);

    // ---- CSR build (overlaps nothing; cheap) ----
    zero_counts_kernel<<<(N_NODES + 255) / 256, 256>>>();
    hist_kernel<<<(N_EDGES + 255) / 256, 256>>>(dst);
    scan_kernel<<<1, 1024>>>();
    scatter_kernel<<<(N_EDGES + 255) / 256, 256>>>(src, dst, rel);

    // ---- per-(node, relation) edge MLP: two relation-batched GEMMs ----
    gemm_kernel<<<dim3(GM, D / BN, NUM_REL), blk>>>(
        feat, 0LL,
        W_rel, (long long)D * D,
        b_rel, (long long)D, nullptr,
        H1, (long long)N_NODES * D,
        N_NODES, D, D, /*act=*/1);

    gemm_kernel<<<dim3(GM, D / BN, NUM_REL), blk>>>(
        H1, (long long)N_NODES * D,
        W_rel, (long long)D * D,
        b_rel, (long long)D, nullptr,
        M2, (long long)N_NODES * D,
        N_NODES, D, D, /*act=*/1);

    // ---- scatter-sum (gather form over CSR) ----
    aggregate_kernel<<<(N_NODES * 32 + 255) / 256, 256>>>();

    // ---- LSTM gates GEMM (bias = b_ih + b_hh fused) + elementwise LSTM ----
    gemm_kernel<<<dim3(GM, D4 / BN, 1), blk>>>(
        agg, 0LL, W_ih, 0LL, b_ih, 0LL, b_hh,
        gates, 0LL, N_NODES, D4, D, /*act=*/0);

    lstm_kernel<<<(N_NODES * D + 255) / 256, 256>>>();

    // ---- global_update MLP ----
    gemm_kernel<<<dim3(GM, HDIM / BN, 1), blk>>>(
        hn, 0LL, W1, 0LL, b1, 0LL, nullptr,
        x1, 0LL, N_NODES, HDIM, D, /*act=*/1);

    gemm_kernel<<<dim3(GM, HDIM / BN, 1), blk>>>(
        x1, 0LL, W2, 0LL, b2, 0LL, nullptr,
        x2, 0LL, N_NODES, HDIM, HDIM, /*act=*/1);

    gemm_kernel<<<dim3(GM, D / BN, 1), blk>>>(
        x2, 0LL, W3, 0LL, b3, 0LL, nullptr,
        out, 0LL, N_NODES, D, HDIM, /*act=*/0);
}

// round 16
// speedup vs baseline: 1.3387x; 1.3387x over previous
#include <cuda_runtime.h>

// ---------------- problem constants ----------------
#define N_NODES 10000
#define N_EDGES 320000
#define D       256
#define G3      768    // gates kept: i, g, o (forget gate dead: c0 = 0)
#define HDIM    128
#define NUM_REL 2

// ---------------- GEMM tiling ----------------
#define BM 128
#define BN 64
#define BK 16
#define TPB 256

// ---------------- scratch (device globals; no allocation allowed) ----------
__device__ float g_H1[NUM_REL * N_NODES * D];    // 20 MB
__device__ float g_M2[NUM_REL * N_NODES * D];    // 20 MB
__device__ float g_agg[N_NODES * D];             // 10 MB
__device__ float g_gates[N_NODES * G3];          // 30 MB  (i,g,o)
__device__ float g_hn[N_NODES * D];              // 10 MB
__device__ float g_x1[N_NODES * HDIM];           // 5 MB
__device__ float g_x2[N_NODES * HDIM];           // 5 MB
__device__ int   g_counts[N_NODES];
__device__ int   g_off[N_NODES];
__device__ int   g_cursor[N_NODES];
__device__ int   g_edges[N_EDGES];

// ---------------- f32x2 packed-FMA helpers (sm_103a) ------------------------
__device__ __forceinline__ void ffma2(unsigned long long& d,
                                      unsigned long long a,
                                      unsigned long long b) {
    asm("fma.rn.f32x2 %0, %1, %2, %0;" : "+l"(d) : "l"(a), "l"(b));
}
__device__ __forceinline__ float2 unpack2(unsigned long long v) {
    unsigned int lo, hi;
    asm("mov.b64 {%0, %1}, %2;" : "=r"(lo), "=r"(hi) : "l"(v));
    return make_float2(__uint_as_float(lo), __uint_as_float(hi));
}

// ---------------- GEMM: C[M,N] = act(A[M,K] @ B[N,K]^T + bias (+bias2)) ----
// 128x64 block tile, BK=16, 256 threads, 8x4 micro-tile, packed f32x2 FMAs.
// A pre-duplicated into smem as (a,a) float2 pairs -> no pack movs in the
// inner loop. Double-buffered smem, register prefetch, ONE sync per tile.
__global__ __launch_bounds__(TPB, 2)
void gemm_kernel(const float* __restrict__ A, long long aZ,
                 const float* __restrict__ B, long long bZ,
                 const float* __restrict__ bias, long long biasZ,
                 const float* __restrict__ bias2,
                 float* __restrict__ C, long long cZ,
                 int M, int N, int K, int ldc, int act)
{
    __shared__ __align__(16) float2 AsD[2][BK][BM + 2];  // dup pairs, pad->16B planes
    __shared__ __align__(16) float  Bs [2][BK][BN + 4];  // pad vs store conflicts

    const int z = blockIdx.z;
    A    += (long long)z * aZ;
    B    += (long long)z * bZ;
    bias += (long long)z * biasZ;
    C    += (long long)z * cZ;

    const int t  = threadIdx.x;
    const int tx = t & 15;             // 16 groups of 4 output cols
    const int ty = t >> 4;             // 16 groups of 8 output rows
    const int m0 = blockIdx.x * BM;
    const int n0 = blockIdx.y * BN;

    // Global staging mapping:
    // A tile: 128x16 floats = 512 float4; thread loads 2 (rows r and r+64)
    const int ar = t >> 2;             // 0..63
    const int ak = (t & 3) * 4;        // 0,4,8,12
    // B tile: 64x16 floats = 256 float4; thread loads 1
    const int br = t >> 2;             // 0..63
    const int bk = (t & 3) * 4;

    const float* Ap0 = A + (long long)(m0 + ar)      * K + ak;
    const float* Ap1 = A + (long long)(m0 + ar + 64) * K + ak;
    const float* Bp  = B + (long long)(n0 + br)      * K + bk;
    const bool av0 = (m0 + ar)      < M;
    const bool av1 = (m0 + ar + 64) < M;

    unsigned long long acc[8][2];
#pragma unroll
    for (int i = 0; i < 8; i++) { acc[i][0] = 0ULL; acc[i][1] = 0ULL; }

    const float4 z4 = make_float4(0.f, 0.f, 0.f, 0.f);

    // ---- stage tile 0 ----
    {
        float4 a0 = av0 ? *(const float4*)Ap0 : z4;
        float4 a1 = av1 ? *(const float4*)Ap1 : z4;
        float4 b0 = *(const float4*)Bp;
        AsD[0][ak + 0][ar]      = make_float2(a0.x, a0.x);
        AsD[0][ak + 1][ar]      = make_float2(a0.y, a0.y);
        AsD[0][ak + 2][ar]      = make_float2(a0.z, a0.z);
        AsD[0][ak + 3][ar]      = make_float2(a0.w, a0.w);
        AsD[0][ak + 0][ar + 64] = make_float2(a1.x, a1.x);
        AsD[0][ak + 1][ar + 64] = make_float2(a1.y, a1.y);
        AsD[0][ak + 2][ar + 64] = make_float2(a1.z, a1.z);
        AsD[0][ak + 3][ar + 64] = make_float2(a1.w, a1.w);
        Bs[0][bk + 0][br] = b0.x;
        Bs[0][bk + 1][br] = b0.y;
        Bs[0][bk + 2][br] = b0.z;
        Bs[0][bk + 3][br] = b0.w;
    }
    __syncthreads();

    const int T = K / BK;
    int buf = 0;
    for (int tile = 0; tile < T; ++tile) {
        // ---- prefetch next tile's global data into registers ----
        float4 na0 = z4, na1 = z4, nb0 = z4;
        const bool pf = (tile + 1) < T;
        if (pf) {
            const int ko = (tile + 1) * BK;
            na0 = av0 ? *(const float4*)(Ap0 + ko) : z4;
            na1 = av1 ? *(const float4*)(Ap1 + ko) : z4;
            nb0 = *(const float4*)(Bp + ko);
        }

        // ---- 8x4 micro-kernel over BK: pure LDS + FFMA2 ----
#pragma unroll
        for (int k = 0; k < BK; k++) {
            const ulonglong2* ap =
                reinterpret_cast<const ulonglong2*>(&AsD[buf][k][ty * 8]);
            ulonglong2 a01 = ap[0];
            ulonglong2 a23 = ap[1];
            ulonglong2 a45 = ap[2];
            ulonglong2 a67 = ap[3];
            ulonglong2 bb =
                *reinterpret_cast<const ulonglong2*>(&Bs[buf][k][tx * 4]);
            ffma2(acc[0][0], a01.x, bb.x); ffma2(acc[0][1], a01.x, bb.y);
            ffma2(acc[1][0], a01.y, bb.x); ffma2(acc[1][1], a01.y, bb.y);
            ffma2(acc[2][0], a23.x, bb.x); ffma2(acc[2][1], a23.x, bb.y);
            ffma2(acc[3][0], a23.y, bb.x); ffma2(acc[3][1], a23.y, bb.y);
            ffma2(acc[4][0], a45.x, bb.x); ffma2(acc[4][1], a45.x, bb.y);
            ffma2(acc[5][0], a45.y, bb.x); ffma2(acc[5][1], a45.y, bb.y);
            ffma2(acc[6][0], a67.x, bb.x); ffma2(acc[6][1], a67.x, bb.y);
            ffma2(acc[7][0], a67.y, bb.x); ffma2(acc[7][1], a67.y, bb.y);
        }

        // ---- store prefetched tile into the other buffer ----
        if (pf) {
            const int nb = buf ^ 1;
            AsD[nb][ak + 0][ar]      = make_float2(na0.x, na0.x);
            AsD[nb][ak + 1][ar]      = make_float2(na0.y, na0.y);
            AsD[nb][ak + 2][ar]      = make_float2(na0.z, na0.z);
            AsD[nb][ak + 3][ar]      = make_float2(na0.w, na0.w);
            AsD[nb][ak + 0][ar + 64] = make_float2(na1.x, na1.x);
            AsD[nb][ak + 1][ar + 64] = make_float2(na1.y, na1.y);
            AsD[nb][ak + 2][ar + 64] = make_float2(na1.z, na1.z);
            AsD[nb][ak + 3][ar + 64] = make_float2(na1.w, na1.w);
            Bs[nb][bk + 0][br] = nb0.x;
            Bs[nb][bk + 1][br] = nb0.y;
            Bs[nb][bk + 2][br] = nb0.z;
            Bs[nb][bk + 3][br] = nb0.w;
            buf = nb;
        }
        __syncthreads();
    }

    // ---- epilogue ----
    float bv[4];
#pragma unroll
    for (int j = 0; j < 4; j++) {
        int c = n0 + tx * 4 + j;
        float b = bias[c];
        if (bias2) b += bias2[c];
        bv[j] = b;
    }
#pragma unroll
    for (int i = 0; i < 8; i++) {
        int row = m0 + ty * 8 + i;
        if (row < M) {
            float2 p0 = unpack2(acc[i][0]);
            float2 p1 = unpack2(acc[i][1]);
            float4 o = make_float4(p0.x + bv[0], p0.y + bv[1],
                                   p1.x + bv[2], p1.y + bv[3]);
            if (act) {
                o.x = fmaxf(o.x, 0.f); o.y = fmaxf(o.y, 0.f);
                o.z = fmaxf(o.z, 0.f); o.w = fmaxf(o.w, 0.f);
            }
            *(float4*)&C[(long long)row * ldc + n0 + tx * 4] = o;
        }
    }
}

// ---------------- CSR construction ----------------
__global__ void zero_counts_kernel() {
    int i = blockIdx.x * blockDim.x + threadIdx.x;
    if (i < N_NODES) g_counts[i] = 0;
}

__global__ void hist_kernel(const int* __restrict__ dst) {
    int e = blockIdx.x * blockDim.x + threadIdx.x;
    if (e < N_EDGES) atomicAdd(&g_counts[dst[e]], 1);
}

__global__ void scan_kernel() {
    __shared__ int sums[1024];
    const int t = threadIdx.x;
    const int CH = (N_NODES + 1023) / 1024;
    const int base = t * CH;
    int s = 0;
#pragma unroll
    for (int i = 0; i < CH; i++)
        if (base + i < N_NODES) s += g_counts[base + i];
    sums[t] = s;
    __syncthreads();
    for (int off = 1; off < 1024; off <<= 1) {
        int v = (t >= off) ? sums[t - off] : 0;
        __syncthreads();
        sums[t] += v;
        __syncthreads();
    }
    int ex = (t == 0) ? 0 : sums[t - 1];
#pragma unroll
    for (int i = 0; i < CH; i++) {
        int n = base + i;
        if (n < N_NODES) {
            g_off[n]    = ex;
            g_cursor[n] = ex;
            ex += g_counts[n];
        }
    }
}

__global__ void scatter_kernel(const int* __restrict__ src,
                               const int* __restrict__ dst,
                               const int* __restrict__ rel) {
    int e = blockIdx.x * blockDim.x + threadIdx.x;
    if (e < N_EDGES) {
        int d   = dst[e];
        int pos = atomicAdd(&g_cursor[d], 1);
        g_edges[pos] = (rel[e] << 16) | src[e];
    }
}

// ---------------- aggregation: one warp per destination node ---------------
__global__ void aggregate_kernel() {
    int node = (blockIdx.x * blockDim.x + threadIdx.x) >> 5;
    int lane = threadIdx.x & 31;
    if (node >= N_NODES) return;
    int start = g_off[node];
    int cnt   = g_counts[node];
    float4 a0 = make_float4(0.f, 0.f, 0.f, 0.f);
    float4 a1 = a0;
    for (int e = 0; e < cnt; e++) {
        int p = g_edges[start + e];
        const float4* row = (const float4*)
            &g_M2[((long long)(p >> 16) * N_NODES + (p & 0xFFFF)) * D];
        float4 v0 = row[lane];
        float4 v1 = row[lane + 32];
        a0.x += v0.x; a0.y += v0.y; a0.z += v0.z; a0.w += v0.w;
        a1.x += v1.x; a1.y += v1.y; a1.z += v1.z; a1.w += v1.w;
    }
    float4* outp = (float4*)&g_agg[(long long)node * D];
    outp[lane]      = a0;
    outp[lane + 32] = a1;
}

// ---------------- per-node LSTM step from zero state ----------------
__device__ __forceinline__ float sigmoidf_(float x) {
    return 1.f / (1.f + expf(-x));
}

__global__ void lstm_kernel() {
    int idx = blockIdx.x * blockDim.x + threadIdx.x;
    if (idx >= N_NODES * D) return;
    int n = idx >> 8;
    int d = idx & 255;
    const float* g = &g_gates[(long long)n * G3];   // layout: i | g | o
    float c = sigmoidf_(g[d]) * tanhf(g[256 + d]);
    g_hn[idx] = sigmoidf_(g[512 + d]) * tanhf(c);
}

// ---------------- launch ----------------
extern "C" void kernel_launch(void* const* d_in, const int* in_sizes, int n_in,
                              void* d_out, int out_size)
{
    const float* feat  = (const float*)d_in[0];
    const int*   src   = (const int*)  d_in[1];
    const int*   dst   = (const int*)  d_in[2];
    const int*   rel   = (const int*)  d_in[3];
    const float* W_rel = (const float*)d_in[4];
    const float* b_rel = (const float*)d_in[5];
    const float* W_ih  = (const float*)d_in[6];
    const float* b_ih  = (const float*)d_in[7];
    const float* b_hh  = (const float*)d_in[8];
    const float* W1    = (const float*)d_in[9];
    const float* b1    = (const float*)d_in[10];
    const float* W2    = (const float*)d_in[11];
    const float* b2    = (const float*)d_in[12];
    const float* W3    = (const float*)d_in[13];
    const float* b3    = (const float*)d_in[14];
    float*       out   = (float*)d_out;

    float *H1, *M2, *agg, *gates, *hn, *x1, *x2;
    cudaGetSymbolAddress((void**)&H1,    g_H1);
    cudaGetSymbolAddress((void**)&M2,    g_M2);
    cudaGetSymbolAddress((void**)&agg,   g_agg);
    cudaGetSymbolAddress((void**)&gates, g_gates);
    cudaGetSymbolAddress((void**)&hn,    g_hn);
    cudaGetSymbolAddress((void**)&x1,    g_x1);
    cudaGetSymbolAddress((void**)&x2,    g_x2);

    const int GM = (N_NODES + BM - 1) / BM;   // 79
    dim3 blk(TPB);

    // ---- CSR build ----
    zero_counts_kernel<<<(N_NODES + 255) / 256, 256>>>();
    hist_kernel<<<(N_EDGES + 255) / 256, 256>>>(dst);
    scan_kernel<<<1, 1024>>>();
    scatter_kernel<<<(N_EDGES + 255) / 256, 256>>>(src, dst, rel);

    // ---- per-(node, relation) edge MLP: two relation-batched GEMMs ----
    gemm_kernel<<<dim3(GM, D / BN, NUM_REL), blk>>>(
        feat, 0LL, W_rel, (long long)D * D, b_rel, (long long)D, nullptr,
        H1, (long long)N_NODES * D, N_NODES, D, D, D, /*act=*/1);

    gemm_kernel<<<dim3(GM, D / BN, NUM_REL), blk>>>(
        H1, (long long)N_NODES * D, W_rel, (long long)D * D,
        b_rel, (long long)D, nullptr,
        M2, (long long)N_NODES * D, N_NODES, D, D, D, /*act=*/1);

    // ---- scatter-sum (gather form over CSR) ----
    aggregate_kernel<<<(N_NODES * 32 + 255) / 256, 256>>>();

    // ---- LSTM gates (forget gate skipped: rows i, then g|o) ----
    gemm_kernel<<<dim3(GM, 256 / BN, 1), blk>>>(
        agg, 0LL, W_ih, 0LL, b_ih, 0LL, b_hh,
        gates, 0LL, N_NODES, 256, D, G3, /*act=*/0);

    gemm_kernel<<<dim3(GM, 512 / BN, 1), blk>>>(
        agg, 0LL, W_ih + 512 * D, 0LL, b_ih + 512, 0LL, b_hh + 512,
        gates + 256, 0LL, N_NODES, 512, D, G3, /*act=*/0);

    lstm_kernel<<<(N_NODES * D + 255) / 256, 256>>>();

    // ---- global_update MLP ----
    gemm_kernel<<<dim3(GM, HDIM / BN, 1), blk>>>(
        hn, 0LL, W1, 0LL, b1, 0LL, nullptr,
        x1, 0LL, N_NODES, HDIM, D, HDIM, /*act=*/1);

    gemm_kernel<<<dim3(GM, HDIM / BN, 1), blk>>>(
        x1, 0LL, W2, 0LL, b2, 0LL, nullptr,
        x2, 0LL, N_NODES, HDIM, HDIM, HDIM, /*act=*/1);

    gemm_kernel<<<dim3(GM, D / BN, 1), blk>>>(
        x2, 0LL, W3, 0LL, b3, 0LL, nullptr,
        out, 0LL, N_NODES, D, HDIM, D, /*act=*/0);
}